// round 15
// baseline (speedup 1.0000x reference)
#include <cuda_runtime.h>
#include <cstdint>

#define Bq 64
#define Tq 512
#define Dq 1024
#define Mq (Bq*Tq)

// ---- scratch (device globals: allocation-free) ----
__device__ float g_xtau[Tq*Bq*Dq];   // [t][b][d]
__device__ float g_mem [Tq*Bq*Dq];   // [t][b][d]
__device__ float g_tauT[2*Dq*Bq];    // ping-pong, TRANSPOSED [p][d][b]
__device__ unsigned g_count2[64] = {0};   // [bblock*32] padded (no false sharing)
__device__ unsigned g_epoch2[64] = {0};

typedef unsigned long long ull;

__device__ __forceinline__ ull pk2(float lo, float hi) {
    ull r; asm("mov.b64 %0, {%1,%2};" : "=l"(r) : "f"(lo), "f"(hi)); return r;
}
__device__ __forceinline__ void upk2(ull a, float& lo, float& hi) {
    asm("mov.b64 {%0,%1}, %2;" : "=f"(lo), "=f"(hi) : "l"(a));
}
__device__ __forceinline__ ull fma2(ull a, ull b, ull c) {
    ull d; asm("fma.rn.f32x2 %0, %1, %2, %3;" : "=l"(d) : "l"(a), "l"(b), "l"(c)); return d;
}
__device__ __forceinline__ ull add2(ull a, ull b) {
    ull d; asm("add.rn.f32x2 %0, %1, %2;" : "=l"(d) : "l"(a), "l"(b)); return d;
}
__device__ __forceinline__ float sigm(float x) { return 1.0f / (1.0f + expf(-x)); }

__device__ __forceinline__ unsigned ld_acq(unsigned* p) {
    unsigned v; asm volatile("ld.acquire.gpu.u32 %0, [%1];" : "=r"(v) : "l"(p) : "memory");
    return v;
}
__device__ __forceinline__ void st_rel(unsigned* p, unsigned v) {
    asm volatile("st.release.gpu.u32 [%0], %1;" :: "l"(p), "r"(v) : "memory");
}

// ============================================================
// Sub-grid barrier over 64 CTAs of one b-block. syncthreads
// first; fence+arrive by thread 0 only (CTA barrier + fence
// cumulativity publishes all threads' writes). Bounded spin.
// ============================================================
__device__ __forceinline__ void gbar(int idx, unsigned nctas) {
    __syncthreads();
    if (threadIdx.x == 0) {
        __threadfence();
        unsigned* cnt = &g_count2[idx * 32];
        unsigned* epo = &g_epoch2[idx * 32];
        unsigned e = ld_acq(epo);
        if (atomicAdd(cnt, 1) == nctas - 1) {
            *cnt = 0;
            st_rel(epo, e + 1);
        } else {
            unsigned guard = 0;
            while (ld_acq(epo) == e) {
                if (++guard > (1u << 20)) break;   // ~130ms escape hatch
                __nanosleep(32);
            }
        }
    }
    __syncthreads();
}

// ============================================================
// Phase 1: big GEMMs (at FFMA2 issue floor; unchanged)
// ============================================================
__global__ __launch_bounds__(256, 1) void gemm_kernel(
    const float* __restrict__ x,
    const float* __restrict__ Wt, const float* __restrict__ bt,
    const float* __restrict__ Wm, const float* __restrict__ bm)
{
    const int z = blockIdx.z;
    const float* __restrict__ W    = z ? Wm : Wt;
    const float* __restrict__ bias = z ? bm : bt;
    float* __restrict__ out        = z ? g_mem : g_xtau;

    __shared__ ull As2[8 * 128];
    __shared__ ull Bs2[8 * 64];

    const int tid = threadIdx.x;
    const int tx = tid & 15, ty = tid >> 4;
    const int m0 = blockIdx.y * 128;
    const int n0 = blockIdx.x * 128;

    const int ar  = tid >> 1;
    const int kc  = (tid & 1) * 4;
    const int brk = tid >> 5;
    const int bc  = tid & 31;

    ull acc[8][4];
#pragma unroll
    for (int i = 0; i < 8; i++)
#pragma unroll
        for (int j = 0; j < 4; j++) acc[i][j] = 0ull;

    for (int k0 = 0; k0 < Dq; k0 += 8) {
        float4 av = *(const float4*)&x[(size_t)(m0 + ar) * Dq + k0 + kc];
        float4 bv = *(const float4*)&W[(size_t)(k0 + brk) * Dq + n0 + bc * 4];
        __syncthreads();
        As2[(kc + 0) * 128 + ar] = pk2(av.x, av.x);
        As2[(kc + 1) * 128 + ar] = pk2(av.y, av.y);
        As2[(kc + 2) * 128 + ar] = pk2(av.z, av.z);
        As2[(kc + 3) * 128 + ar] = pk2(av.w, av.w);
        Bs2[brk * 64 + bc * 2 + 0] = pk2(bv.x, bv.y);
        Bs2[brk * 64 + bc * 2 + 1] = pk2(bv.z, bv.w);
        __syncthreads();
#pragma unroll
        for (int k = 0; k < 8; k++) {
            ulonglong2 a01 = *(const ulonglong2*)&As2[k * 128 + ty * 8 + 0];
            ulonglong2 a23 = *(const ulonglong2*)&As2[k * 128 + ty * 8 + 2];
            ulonglong2 a45 = *(const ulonglong2*)&As2[k * 128 + ty * 8 + 4];
            ulonglong2 a67 = *(const ulonglong2*)&As2[k * 128 + ty * 8 + 6];
            ulonglong2 b01 = *(const ulonglong2*)&Bs2[k * 64 + tx * 4 + 0];
            ulonglong2 b23 = *(const ulonglong2*)&Bs2[k * 64 + tx * 4 + 2];
            ull a[8] = {a01.x, a01.y, a23.x, a23.y, a45.x, a45.y, a67.x, a67.y};
            ull b[4] = {b01.x, b01.y, b23.x, b23.y};
#pragma unroll
            for (int i = 0; i < 8; i++)
#pragma unroll
                for (int j = 0; j < 4; j++)
                    acc[i][j] = fma2(a[i], b[j], acc[i][j]);
        }
    }

    float bl[8];
#pragma unroll
    for (int j = 0; j < 8; j++) bl[j] = bias[n0 + tx * 8 + j];

#pragma unroll
    for (int i = 0; i < 8; i++) {
        int m = m0 + ty * 8 + i;
        int bb = m >> 9;
        int tt = m & 511;
        float r[8];
#pragma unroll
        for (int j = 0; j < 4; j++) upk2(acc[i][j], r[2 * j], r[2 * j + 1]);
#pragma unroll
        for (int j = 0; j < 8; j++) r[j] += bl[j];
        float* orow = out + (size_t)(tt * Bq + bb) * Dq + n0 + tx * 8;
        *(float4*)&orow[0] = make_float4(r[0], r[1], r[2], r[3]);
        *(float4*)&orow[4] = make_float4(r[4], r[5], r[6], r[7]);
    }
}

// ---- dynamic smem layout for scan ----
#define OFF_W    0                       // 64KB weights: 16 cols = 8 colpairs x 1024 k
#define OFF_RED  65536                   // 36.9KB [kc 16][b 32][9] padded partials
#define OFF_DOT  (65536 + 36864)         // 2KB reduced dots [b 32][16 cols]
#define SCAN_SMEM (OFF_DOT + 2048)       // 104448 B

// ============================================================
// Phase 2: PERSISTENT scan, batch-split grid.
// 128 CTAs = 64 col-blocks (16 cols each) x 2 b-blocks (32 b).
// Per-CTA tau traffic halves; barrier is per-b-block (64 CTAs).
// Dot: thread (b_loc 32, kc 16), k in [kc*64, +64).
// Dynamics: thread (db 32, dj 16), one (batch, col) each;
// v/thresh in registers for all 512 steps.
// ============================================================
__global__ __launch_bounds__(512, 1) void scan_kernel(
    const float* __restrict__ Wt,
    const float* __restrict__ log_thresh,
    float* __restrict__ out)
{
    extern __shared__ char smem[];
    ull* sW = (ull*)(smem + OFF_W);
    ull (*sRed)[32][9] = (ull(*)[32][9])(smem + OFF_RED);
    float* sDot = (float*)(smem + OFF_DOT);

    const int tid = threadIdx.x;
    const int cb  = blockIdx.x & 63;       // col-block
    const int bbs = blockIdx.x >> 6;       // b-block 0/1
    const int n0  = cb * 16;
    const int bb0 = bbs * 32;

    const int b_loc = tid & 31;            // dot role
    const int kc    = tid >> 5;            // 0..15
    const int db    = tid >> 4;            // dynamics role: batch 0..31
    const int dj    = tid & 15;            // col 0..15
    const int gb    = bb0 + db;            // global batch

    // ---- one-time: weight slice Wt_tau[:, n0:n0+16] -> smem ----
#pragma unroll
    for (int r = 0; r < 8; r++) {
        int idx = r * 512 + tid;           // 0..4095
        int k = idx >> 2, h = idx & 3;
        float4 w = __ldg((const float4*)&Wt[(size_t)(Dq + k) * Dq + n0 + h * 4]);
        sW[k * 8 + h * 2 + 0] = pk2(w.x, w.y);
        sW[k * 8 + h * 2 + 1] = pk2(w.z, w.w);
    }

    // ---- one-time: per-thread v/thresh regs, tau init ----
    float vv = 0.0f;
    float th = sigm(__ldg(&log_thresh[n0 + dj]));
    g_tauT[(size_t)(n0 + dj) * Bq + gb] = 1.0f;
    if (bbs == 0 && tid < 16)
        out[(size_t)Mq * Dq + 2 * Bq * Dq + n0 + tid] = sigm(__ldg(&log_thresh[n0 + tid]));

    gbar(bbs, 64);

    for (int t = 0; t < Tq; t++) {
        const int ping = t & 1;

        // prefetch dynamics inputs (overlap the dot)
        float xv = __ldcg(&g_xtau[(size_t)(t * Bq + gb) * Dq + n0 + dj]);
        float mv = __ldcg(&g_mem [(size_t)(t * Bq + gb) * Dq + n0 + dj]);

        // ---- dot: 16 cols, k in [kc*64, +64), batch bb0+b_loc ----
        const float* __restrict__ tsrc =
            &g_tauT[(size_t)ping * Dq * Bq + bb0 + b_loc];
        ull acc[8];
#pragma unroll
        for (int i = 0; i < 8; i++) acc[i] = 0ull;
#pragma unroll 8
        for (int kk = 0; kk < 64; kk++) {
            int k = kc * 64 + kk;
            float tv = __ldcg(&tsrc[(size_t)k * Bq]);   // coalesced 128B/warp
            ull a = pk2(tv, tv);
            const ull* wp = &sW[k * 8];
            ulonglong2 w01 = *(const ulonglong2*)&wp[0];
            ulonglong2 w23 = *(const ulonglong2*)&wp[2];
            ulonglong2 w45 = *(const ulonglong2*)&wp[4];
            ulonglong2 w67 = *(const ulonglong2*)&wp[6];
            acc[0] = fma2(a, w01.x, acc[0]); acc[1] = fma2(a, w01.y, acc[1]);
            acc[2] = fma2(a, w23.x, acc[2]); acc[3] = fma2(a, w23.y, acc[3]);
            acc[4] = fma2(a, w45.x, acc[4]); acc[5] = fma2(a, w45.y, acc[5]);
            acc[6] = fma2(a, w67.x, acc[6]); acc[7] = fma2(a, w67.y, acc[7]);
        }
        ull* pr = &sRed[kc][b_loc][0];
#pragma unroll
        for (int i = 0; i < 8; i++) pr[i] = acc[i];
        __syncthreads();

        // ---- reduce 16 kc-partials per (b, colpair) ----
        if (tid < 256) {
            int rb = tid & 31, cp = tid >> 5;   // cp 0..7
            ull s = 0;
#pragma unroll
            for (int q = 0; q < 16; q++)
                s = add2(s, sRed[q][rb][cp]);
            float lo, hi; upk2(s, lo, hi);
            sDot[rb * 16 + 2 * cp + 0] = lo;
            sDot[rb * 16 + 2 * cp + 1] = hi;
        }
        __syncthreads();

        // ---- dynamics: one (batch, col) per thread ----
        {
            float dot  = sDot[db * 16 + dj];
            float tauv = sigm(xv + dot);
            float alpha = expf(-1.0f / (tauv + 1e-6f));
            float vn = alpha * vv + (1.0f - alpha) * mv;
            float s = (vn >= th) ? 1.0f : 0.0f;
            vv = vn * (1.0f - s);

            out[((size_t)gb * Tq + t) * Dq + n0 + dj] = s;                 // spikes
            g_tauT[(size_t)(ping ^ 1) * Dq * Bq + (size_t)(n0 + dj) * Bq + gb] = tauv;
            if (t == Tq - 1) {
                out[(size_t)Mq * Dq + (size_t)gb * Dq + n0 + dj] = tauv;   // tau
                out[(size_t)Mq * Dq + (size_t)Bq * Dq + (size_t)gb * Dq + n0 + dj] = vv; // v
            }
        }
        gbar(bbs, 64);
    }
}

// ============================================================
extern "C" void kernel_launch(void* const* d_in, const int* in_sizes, int n_in,
                              void* d_out, int out_size)
{
    const float* x  = (const float*)d_in[0];
    const float* Wt = (const float*)d_in[1];
    const float* bt = (const float*)d_in[2];
    const float* Wm = (const float*)d_in[3];
    const float* bm = (const float*)d_in[4];
    const float* lt = (const float*)d_in[5];
    float* out = (float*)d_out;

    cudaFuncSetAttribute(scan_kernel,
                         cudaFuncAttributeMaxDynamicSharedMemorySize, SCAN_SMEM);

    dim3 ggrid(Dq / 128, Mq / 128, 2);
    gemm_kernel<<<ggrid, 256>>>(x, Wt, bt, Wm, bm);

    scan_kernel<<<128, 512, SCAN_SMEM>>>(Wt, lt, out);
}

// round 16
// speedup vs baseline: 1.0750x; 1.0750x over previous
#include <cuda_runtime.h>
#include <cstdint>

#define Bq 64
#define Tq 512
#define Dq 1024
#define Mq (Bq*Tq)

// ---- scratch (device globals: allocation-free) ----
__device__ float g_xtau[Tq*Bq*Dq];   // [t][b][d]
__device__ float g_mem [Tq*Bq*Dq];   // [t][b][d]
__device__ float g_tauT[2*Dq*Bq];    // ping-pong, TRANSPOSED [p][d][b]
__device__ unsigned g_count2[32] = {0};
__device__ unsigned g_epoch2[32] = {0};

typedef unsigned long long ull;

__device__ __forceinline__ ull pk2(float lo, float hi) {
    ull r; asm("mov.b64 %0, {%1,%2};" : "=l"(r) : "f"(lo), "f"(hi)); return r;
}
__device__ __forceinline__ void upk2(ull a, float& lo, float& hi) {
    asm("mov.b64 {%0,%1}, %2;" : "=f"(lo), "=f"(hi) : "l"(a));
}
__device__ __forceinline__ ull fma2(ull a, ull b, ull c) {
    ull d; asm("fma.rn.f32x2 %0, %1, %2, %3;" : "=l"(d) : "l"(a), "l"(b), "l"(c)); return d;
}
__device__ __forceinline__ ull add2(ull a, ull b) {
    ull d; asm("add.rn.f32x2 %0, %1, %2;" : "=l"(d) : "l"(a), "l"(b)); return d;
}
__device__ __forceinline__ float sigm(float x) { return 1.0f / (1.0f + expf(-x)); }

__device__ __forceinline__ unsigned ld_acq(unsigned* p) {
    unsigned v; asm volatile("ld.acquire.gpu.u32 %0, [%1];" : "=r"(v) : "l"(p) : "memory");
    return v;
}
__device__ __forceinline__ void st_rel(unsigned* p, unsigned v) {
    asm volatile("st.release.gpu.u32 [%0], %1;" :: "l"(p), "r"(v) : "memory");
}

// ============================================================
// Grid barrier (128 CTAs): syncthreads, then thread-0 fence +
// arrive (fence cumulativity publishes all threads' writes).
// Bounded spin: a hang degrades to finite wrong answer.
// ============================================================
__device__ __forceinline__ void gbar(unsigned nctas) {
    __syncthreads();
    if (threadIdx.x == 0) {
        __threadfence();
        unsigned e = ld_acq(&g_epoch2[0]);
        if (atomicAdd(&g_count2[0], 1) == nctas - 1) {
            g_count2[0] = 0;
            st_rel(&g_epoch2[0], e + 1);
        } else {
            unsigned guard = 0;
            while (ld_acq(&g_epoch2[0]) == e) {
                if (++guard > (1u << 20)) break;   // ~130ms escape hatch
                __nanosleep(32);
            }
        }
    }
    __syncthreads();
}

// ============================================================
// Phase 1: big GEMMs (at FFMA2 issue floor; unchanged)
// ============================================================
__global__ __launch_bounds__(256, 1) void gemm_kernel(
    const float* __restrict__ x,
    const float* __restrict__ Wt, const float* __restrict__ bt,
    const float* __restrict__ Wm, const float* __restrict__ bm)
{
    const int z = blockIdx.z;
    const float* __restrict__ W    = z ? Wm : Wt;
    const float* __restrict__ bias = z ? bm : bt;
    float* __restrict__ out        = z ? g_mem : g_xtau;

    __shared__ ull As2[8 * 128];
    __shared__ ull Bs2[8 * 64];

    const int tid = threadIdx.x;
    const int tx = tid & 15, ty = tid >> 4;
    const int m0 = blockIdx.y * 128;
    const int n0 = blockIdx.x * 128;

    const int ar  = tid >> 1;
    const int kc  = (tid & 1) * 4;
    const int brk = tid >> 5;
    const int bc  = tid & 31;

    ull acc[8][4];
#pragma unroll
    for (int i = 0; i < 8; i++)
#pragma unroll
        for (int j = 0; j < 4; j++) acc[i][j] = 0ull;

    for (int k0 = 0; k0 < Dq; k0 += 8) {
        float4 av = *(const float4*)&x[(size_t)(m0 + ar) * Dq + k0 + kc];
        float4 bv = *(const float4*)&W[(size_t)(k0 + brk) * Dq + n0 + bc * 4];
        __syncthreads();
        As2[(kc + 0) * 128 + ar] = pk2(av.x, av.x);
        As2[(kc + 1) * 128 + ar] = pk2(av.y, av.y);
        As2[(kc + 2) * 128 + ar] = pk2(av.z, av.z);
        As2[(kc + 3) * 128 + ar] = pk2(av.w, av.w);
        Bs2[brk * 64 + bc * 2 + 0] = pk2(bv.x, bv.y);
        Bs2[brk * 64 + bc * 2 + 1] = pk2(bv.z, bv.w);
        __syncthreads();
#pragma unroll
        for (int k = 0; k < 8; k++) {
            ulonglong2 a01 = *(const ulonglong2*)&As2[k * 128 + ty * 8 + 0];
            ulonglong2 a23 = *(const ulonglong2*)&As2[k * 128 + ty * 8 + 2];
            ulonglong2 a45 = *(const ulonglong2*)&As2[k * 128 + ty * 8 + 4];
            ulonglong2 a67 = *(const ulonglong2*)&As2[k * 128 + ty * 8 + 6];
            ulonglong2 b01 = *(const ulonglong2*)&Bs2[k * 64 + tx * 4 + 0];
            ulonglong2 b23 = *(const ulonglong2*)&Bs2[k * 64 + tx * 4 + 2];
            ull a[8] = {a01.x, a01.y, a23.x, a23.y, a45.x, a45.y, a67.x, a67.y};
            ull b[4] = {b01.x, b01.y, b23.x, b23.y};
#pragma unroll
            for (int i = 0; i < 8; i++)
#pragma unroll
                for (int j = 0; j < 4; j++)
                    acc[i][j] = fma2(a[i], b[j], acc[i][j]);
        }
    }

    float bl[8];
#pragma unroll
    for (int j = 0; j < 8; j++) bl[j] = bias[n0 + tx * 8 + j];

#pragma unroll
    for (int i = 0; i < 8; i++) {
        int m = m0 + ty * 8 + i;
        int bb = m >> 9;
        int tt = m & 511;
        float r[8];
#pragma unroll
        for (int j = 0; j < 4; j++) upk2(acc[i][j], r[2 * j], r[2 * j + 1]);
#pragma unroll
        for (int j = 0; j < 8; j++) r[j] += bl[j];
        float* orow = out + (size_t)(tt * Bq + bb) * Dq + n0 + tx * 8;
        *(float4*)&orow[0] = make_float4(r[0], r[1], r[2], r[3]);
        *(float4*)&orow[4] = make_float4(r[4], r[5], r[6], r[7]);
    }
}

// ---- dynamic smem layout for scan ----
#define OFF_W    0                       // 32KB  weights [k][4 ull colpairs]
#define OFF_RED  32768                   // 72KB  [kc 32][bp 32][9 ull] padded
#define OFF_DOT  (32768 + 73728)         // 2KB   reduced dots [b 64][8 cols]
#define SCAN_SMEM (OFF_DOT + 2048)       // 108544 B

// ============================================================
// Phase 2: PERSISTENT scan, 128 CTAs x 1024 threads (8 warps/
// SMSP for latency coverage). CTA owns 8 columns, all 64 b.
// Thread (bp 0..31, kc 0..31): b = {2bp, 2bp+1}, k in
// [kc*32, +32). Weights resident in smem; v/thresh in regs.
// ============================================================
__global__ __launch_bounds__(1024, 1) void scan_kernel(
    const float* __restrict__ Wt,
    const float* __restrict__ log_thresh,
    float* __restrict__ out)
{
    extern __shared__ char smem[];
    ull* sW = (ull*)(smem + OFF_W);
    ull (*sRed)[32][9] = (ull(*)[32][9])(smem + OFF_RED);
    float* sDot = (float*)(smem + OFF_DOT);

    const int tid = threadIdx.x;
    const int n0  = blockIdx.x * 8;
    const int bp  = tid & 31;           // b-pair 0..31
    const int kc  = tid >> 5;           // 0..31
    const int db  = tid >> 3;           // dynamics role: batch 0..127 (use <64 via tid<512)
    const int dj  = tid & 7;            // dynamics col 0..7

    // ---- one-time: weight slice Wt_tau[:, n0:n0+8] -> smem ----
#pragma unroll
    for (int r = 0; r < 2; r++) {
        int idx = r * 1024 + tid;       // 0..2047
        int k = idx >> 1, h = idx & 1;
        float4 w = __ldg((const float4*)&Wt[(size_t)(Dq + k) * Dq + n0 + h * 4]);
        sW[k * 4 + h * 2 + 0] = pk2(w.x, w.y);
        sW[k * 4 + h * 2 + 1] = pk2(w.z, w.w);
    }

    // ---- one-time: per-thread v/thresh regs, tau ping init ----
    float vv = 0.0f, th = 1.0f;
    if (tid < 512) {
        th = sigm(__ldg(&log_thresh[n0 + dj]));
        g_tauT[(size_t)(n0 + dj) * Bq + db] = 1.0f;
    }
    if (tid < 8)
        out[(size_t)Mq * Dq + 2 * Bq * Dq + n0 + tid] = sigm(__ldg(&log_thresh[n0 + tid]));

    gbar(gridDim.x);

    for (int t = 0; t < Tq; t++) {
        const int ping = t & 1;

        // ---- prefetch dynamics inputs (overlap the dot) ----
        float xv = 0.0f, mv = 0.0f;
        if (tid < 512) {
            xv = __ldcg(&g_xtau[(size_t)(t * Bq + db) * Dq + n0 + dj]);
            mv = __ldcg(&g_mem [(size_t)(t * Bq + db) * Dq + n0 + dj]);
        }

        // ---- dot: k in [kc*32, +32), b = {2bp, 2bp+1} ----
        const float2* __restrict__ tau2 = (const float2*)
            (&g_tauT[(size_t)ping * Dq * Bq]) + (size_t)(kc * 32) * 32 + bp;
        const ull* __restrict__ wp = &sW[(size_t)(kc * 32) * 4];

        ull a00 = 0, a01 = 0, a02 = 0, a03 = 0;   // b = 2bp
        ull a10 = 0, a11 = 0, a12 = 0, a13 = 0;   // b = 2bp+1
#pragma unroll 16
        for (int kk = 0; kk < 32; kk++) {
            float2 tv = __ldcg(tau2 + (size_t)kk * 32);     // 256B/warp coalesced
            ulonglong2 w01v = *(const ulonglong2*)&wp[kk * 4 + 0];  // broadcast LDS
            ulonglong2 w23v = *(const ulonglong2*)&wp[kk * 4 + 2];
            ull a = pk2(tv.x, tv.x);
            a00 = fma2(a, w01v.x, a00); a01 = fma2(a, w01v.y, a01);
            a02 = fma2(a, w23v.x, a02); a03 = fma2(a, w23v.y, a03);
            a = pk2(tv.y, tv.y);
            a10 = fma2(a, w01v.x, a10); a11 = fma2(a, w01v.y, a11);
            a12 = fma2(a, w23v.x, a12); a13 = fma2(a, w23v.y, a13);
        }
        ull* pr = &sRed[kc][bp][0];
        pr[0] = a00; pr[1] = a01; pr[2] = a02; pr[3] = a03;
        pr[4] = a10; pr[5] = a11; pr[6] = a12; pr[7] = a13;
        __syncthreads();

        // ---- reduce 32 kc-partials per (b, colpair) ----
        if (tid < 256) {
            int bb = tid >> 2, cp = tid & 3;
            int bpp = bb >> 1, half = (bb & 1) * 4;
            ull s = 0;
#pragma unroll
            for (int q = 0; q < 32; q++)
                s = add2(s, sRed[q][bpp][half + cp]);
            float lo, hi; upk2(s, lo, hi);
            sDot[bb * 8 + 2 * cp + 0] = lo;
            sDot[bb * 8 + 2 * cp + 1] = hi;
        }
        __syncthreads();

        // ---- dynamics: one (batch, col) per thread (tid<512) ----
        if (tid < 512) {
            float dot  = sDot[db * 8 + dj];
            float tauv = sigm(xv + dot);
            float alpha = expf(-1.0f / (tauv + 1e-6f));
            float vn = alpha * vv + (1.0f - alpha) * mv;
            float s = (vn >= th) ? 1.0f : 0.0f;
            vv = vn * (1.0f - s);

            out[((size_t)db * Tq + t) * Dq + n0 + dj] = s;                 // spikes
            g_tauT[(size_t)(ping ^ 1) * Dq * Bq + (size_t)(n0 + dj) * Bq + db] = tauv;
            if (t == Tq - 1) {
                out[(size_t)Mq * Dq + (size_t)db * Dq + n0 + dj] = tauv;   // tau
                out[(size_t)Mq * Dq + (size_t)Bq * Dq + (size_t)db * Dq + n0 + dj] = vv; // v
            }
        }
        gbar(gridDim.x);
    }
}

// ============================================================
extern "C" void kernel_launch(void* const* d_in, const int* in_sizes, int n_in,
                              void* d_out, int out_size)
{
    const float* x  = (const float*)d_in[0];
    const float* Wt = (const float*)d_in[1];
    const float* bt = (const float*)d_in[2];
    const float* Wm = (const float*)d_in[3];
    const float* bm = (const float*)d_in[4];
    const float* lt = (const float*)d_in[5];
    float* out = (float*)d_out;

    cudaFuncSetAttribute(scan_kernel,
                         cudaFuncAttributeMaxDynamicSharedMemorySize, SCAN_SMEM);

    dim3 ggrid(Dq / 128, Mq / 128, 2);
    gemm_kernel<<<ggrid, 256>>>(x, Wt, bt, Wm, bm);

    scan_kernel<<<128, 1024, SCAN_SMEM>>>(Wt, lt, out);
}

// round 17
// speedup vs baseline: 1.0844x; 1.0087x over previous
#include <cuda_runtime.h>
#include <cstdint>

#define Bq 64
#define Tq 512
#define Dq 1024
#define Mq (Bq*Tq)

// ---- scratch (device globals: allocation-free) ----
__device__ float g_xtau[Tq*Bq*Dq];   // [t][b][d]
__device__ float g_mem [Tq*Bq*Dq];   // [t][b][d]
__device__ float g_tauT[2*Dq*Bq];    // ping-pong, TRANSPOSED [p][d][b]
__device__ unsigned g_count2[32] = {0};
__device__ unsigned g_epoch2[32] = {0};

typedef unsigned long long ull;

__device__ __forceinline__ ull pk2(float lo, float hi) {
    ull r; asm("mov.b64 %0, {%1,%2};" : "=l"(r) : "f"(lo), "f"(hi)); return r;
}
__device__ __forceinline__ void upk2(ull a, float& lo, float& hi) {
    asm("mov.b64 {%0,%1}, %2;" : "=f"(lo), "=f"(hi) : "l"(a));
}
__device__ __forceinline__ ull fma2(ull a, ull b, ull c) {
    ull d; asm("fma.rn.f32x2 %0, %1, %2, %3;" : "=l"(d) : "l"(a), "l"(b), "l"(c)); return d;
}
__device__ __forceinline__ ull add2(ull a, ull b) {
    ull d; asm("add.rn.f32x2 %0, %1, %2;" : "=l"(d) : "l"(a), "l"(b)); return d;
}
__device__ __forceinline__ float sigm(float x) { return 1.0f / (1.0f + expf(-x)); }

__device__ __forceinline__ unsigned ld_acq(unsigned* p) {
    unsigned v; asm volatile("ld.acquire.gpu.u32 %0, [%1];" : "=r"(v) : "l"(p) : "memory");
    return v;
}
__device__ __forceinline__ void st_rel(unsigned* p, unsigned v) {
    asm volatile("st.release.gpu.u32 [%0], %1;" :: "l"(p), "r"(v) : "memory");
}

// ============================================================
// Full grid barrier (prologue only)
// ============================================================
__device__ __forceinline__ void gbar(unsigned nctas) {
    __syncthreads();
    if (threadIdx.x == 0) {
        __threadfence();
        unsigned e = ld_acq(&g_epoch2[0]);
        if (atomicAdd(&g_count2[0], 1) == nctas - 1) {
            g_count2[0] = 0;
            st_rel(&g_epoch2[0], e + 1);
        } else {
            unsigned guard = 0;
            while (ld_acq(&g_epoch2[0]) == e) {
                if (++guard > (1u << 20)) break;
                __nanosleep(32);
            }
        }
    }
    __syncthreads();
}

// ============================================================
// Phase 1: big GEMMs (at FFMA2 issue floor; unchanged)
// ============================================================
__global__ __launch_bounds__(256, 1) void gemm_kernel(
    const float* __restrict__ x,
    const float* __restrict__ Wt, const float* __restrict__ bt,
    const float* __restrict__ Wm, const float* __restrict__ bm)
{
    const int z = blockIdx.z;
    const float* __restrict__ W    = z ? Wm : Wt;
    const float* __restrict__ bias = z ? bm : bt;
    float* __restrict__ out        = z ? g_mem : g_xtau;

    __shared__ ull As2[8 * 128];
    __shared__ ull Bs2[8 * 64];

    const int tid = threadIdx.x;
    const int tx = tid & 15, ty = tid >> 4;
    const int m0 = blockIdx.y * 128;
    const int n0 = blockIdx.x * 128;

    const int ar  = tid >> 1;
    const int kc  = (tid & 1) * 4;
    const int brk = tid >> 5;
    const int bc  = tid & 31;

    ull acc[8][4];
#pragma unroll
    for (int i = 0; i < 8; i++)
#pragma unroll
        for (int j = 0; j < 4; j++) acc[i][j] = 0ull;

    for (int k0 = 0; k0 < Dq; k0 += 8) {
        float4 av = *(const float4*)&x[(size_t)(m0 + ar) * Dq + k0 + kc];
        float4 bv = *(const float4*)&W[(size_t)(k0 + brk) * Dq + n0 + bc * 4];
        __syncthreads();
        As2[(kc + 0) * 128 + ar] = pk2(av.x, av.x);
        As2[(kc + 1) * 128 + ar] = pk2(av.y, av.y);
        As2[(kc + 2) * 128 + ar] = pk2(av.z, av.z);
        As2[(kc + 3) * 128 + ar] = pk2(av.w, av.w);
        Bs2[brk * 64 + bc * 2 + 0] = pk2(bv.x, bv.y);
        Bs2[brk * 64 + bc * 2 + 1] = pk2(bv.z, bv.w);
        __syncthreads();
#pragma unroll
        for (int k = 0; k < 8; k++) {
            ulonglong2 a01 = *(const ulonglong2*)&As2[k * 128 + ty * 8 + 0];
            ulonglong2 a23 = *(const ulonglong2*)&As2[k * 128 + ty * 8 + 2];
            ulonglong2 a45 = *(const ulonglong2*)&As2[k * 128 + ty * 8 + 4];
            ulonglong2 a67 = *(const ulonglong2*)&As2[k * 128 + ty * 8 + 6];
            ulonglong2 b01 = *(const ulonglong2*)&Bs2[k * 64 + tx * 4 + 0];
            ulonglong2 b23 = *(const ulonglong2*)&Bs2[k * 64 + tx * 4 + 2];
            ull a[8] = {a01.x, a01.y, a23.x, a23.y, a45.x, a45.y, a67.x, a67.y};
            ull b[4] = {b01.x, b01.y, b23.x, b23.y};
#pragma unroll
            for (int i = 0; i < 8; i++)
#pragma unroll
                for (int j = 0; j < 4; j++)
                    acc[i][j] = fma2(a[i], b[j], acc[i][j]);
        }
    }

    float bl[8];
#pragma unroll
    for (int j = 0; j < 8; j++) bl[j] = bias[n0 + tx * 8 + j];

#pragma unroll
    for (int i = 0; i < 8; i++) {
        int m = m0 + ty * 8 + i;
        int bb = m >> 9;
        int tt = m & 511;
        float r[8];
#pragma unroll
        for (int j = 0; j < 4; j++) upk2(acc[i][j], r[2 * j], r[2 * j + 1]);
#pragma unroll
        for (int j = 0; j < 8; j++) r[j] += bl[j];
        float* orow = out + (size_t)(tt * Bq + bb) * Dq + n0 + tx * 8;
        *(float4*)&orow[0] = make_float4(r[0], r[1], r[2], r[3]);
        *(float4*)&orow[4] = make_float4(r[4], r[5], r[6], r[7]);
    }
}

// ---- dynamic smem layout for scan ----
#define OFF_W    0                       // 32KB  weights [k][4 ull colpairs]
#define OFF_RED  32768                   // 72KB  [kc 32][bp 32][9 ull] padded
#define OFF_DOT  (32768 + 73728)         // 2KB   reduced dots [b 64][8 cols]
#define SCAN_SMEM (OFF_DOT + 2048)       // 108544 B

// ============================================================
// Phase 2: PERSISTENT scan, 128 CTAs x 1024 threads.
// Critical-path-minimized step: tau is computed and published
// FIRST; the barrier arrival (thread 1023, a non-dynamics
// thread) happens immediately after; the exp/v/spike tail and
// the next step's xv/mv prefetch run UNDER the barrier wait.
// ============================================================
__global__ __launch_bounds__(1024, 1) void scan_kernel(
    const float* __restrict__ Wt,
    const float* __restrict__ log_thresh,
    float* __restrict__ out)
{
    extern __shared__ char smem[];
    ull* sW = (ull*)(smem + OFF_W);
    ull (*sRed)[32][9] = (ull(*)[32][9])(smem + OFF_RED);
    float* sDot = (float*)(smem + OFF_DOT);

    const int tid = threadIdx.x;
    const int n0  = blockIdx.x * 8;
    const int bp  = tid & 31;           // b-pair 0..31
    const int kc  = tid >> 5;           // 0..31
    const int db  = tid >> 3;           // dynamics batch (tid<512)
    const int dj  = tid & 7;            // dynamics col 0..7
    const unsigned nctas = gridDim.x;

    // ---- one-time: weight slice Wt_tau[:, n0:n0+8] -> smem ----
#pragma unroll
    for (int r = 0; r < 2; r++) {
        int idx = r * 1024 + tid;       // 0..2047
        int k = idx >> 1, h = idx & 1;
        float4 w = __ldg((const float4*)&Wt[(size_t)(Dq + k) * Dq + n0 + h * 4]);
        sW[k * 4 + h * 2 + 0] = pk2(w.x, w.y);
        sW[k * 4 + h * 2 + 1] = pk2(w.z, w.w);
    }

    // ---- one-time: per-thread v/thresh regs, tau ping init ----
    float vv = 0.0f, th = 1.0f;
    if (tid < 512) {
        th = sigm(__ldg(&log_thresh[n0 + dj]));
        g_tauT[(size_t)(n0 + dj) * Bq + db] = 1.0f;
    }
    if (tid < 8)
        out[(size_t)Mq * Dq + 2 * Bq * Dq + n0 + tid] = sigm(__ldg(&log_thresh[n0 + tid]));

    gbar(nctas);

    // ---- prologue prefetch of step-0 dynamics inputs ----
    float xv = 0.0f, mv = 0.0f;
    if (tid < 512) {
        xv = __ldcg(&g_xtau[(size_t)(0 * Bq + db) * Dq + n0 + dj]);
        mv = __ldcg(&g_mem [(size_t)(0 * Bq + db) * Dq + n0 + dj]);
    }

    for (int t = 0; t < Tq; t++) {
        const int ping = t & 1;

        // ---- dot: k in [kc*32, +32), b = {2bp, 2bp+1} ----
        const float2* __restrict__ tau2 = (const float2*)
            (&g_tauT[(size_t)ping * Dq * Bq]) + (size_t)(kc * 32) * 32 + bp;
        const ull* __restrict__ wp = &sW[(size_t)(kc * 32) * 4];

        ull a00 = 0, a01 = 0, a02 = 0, a03 = 0;   // b = 2bp
        ull a10 = 0, a11 = 0, a12 = 0, a13 = 0;   // b = 2bp+1
#pragma unroll 16
        for (int kk = 0; kk < 32; kk++) {
            float2 tv = __ldcg(tau2 + (size_t)kk * 32);
            ulonglong2 w01v = *(const ulonglong2*)&wp[kk * 4 + 0];
            ulonglong2 w23v = *(const ulonglong2*)&wp[kk * 4 + 2];
            ull a = pk2(tv.x, tv.x);
            a00 = fma2(a, w01v.x, a00); a01 = fma2(a, w01v.y, a01);
            a02 = fma2(a, w23v.x, a02); a03 = fma2(a, w23v.y, a03);
            a = pk2(tv.y, tv.y);
            a10 = fma2(a, w01v.x, a10); a11 = fma2(a, w01v.y, a11);
            a12 = fma2(a, w23v.x, a12); a13 = fma2(a, w23v.y, a13);
        }
        ull* pr = &sRed[kc][bp][0];
        pr[0] = a00; pr[1] = a01; pr[2] = a02; pr[3] = a03;
        pr[4] = a10; pr[5] = a11; pr[6] = a12; pr[7] = a13;
        __syncthreads();

        // ---- reduce 32 kc-partials per (b, colpair) ----
        if (tid < 256) {
            int bb = tid >> 2, cp = tid & 3;
            int bpp = bb >> 1, half = (bb & 1) * 4;
            ull s = 0;
#pragma unroll
            for (int q = 0; q < 32; q++)
                s = add2(s, sRed[q][bpp][half + cp]);
            float lo, hi; upk2(s, lo, hi);
            sDot[bb * 8 + 2 * cp + 0] = lo;
            sDot[bb * 8 + 2 * cp + 1] = hi;
        }
        __syncthreads();

        // ---- CRITICAL PATH: tau only. Compute + publish. ----
        float tauv = 0.0f;
        if (tid < 512) {
            tauv = sigm(xv + sDot[db * 8 + dj]);
            g_tauT[(size_t)(ping ^ 1) * Dq * Bq + (size_t)(n0 + dj) * Bq + db] = tauv;
            if (t == Tq - 1)
                out[(size_t)Mq * Dq + (size_t)db * Dq + n0 + dj] = tauv;
        }
        __syncthreads();                        // tau stores done CTA-wide

        // ---- barrier arrival ASAP (thread 1023; fence covers peers) ----
        unsigned e = 0; bool released = false;
        if (tid == 1023) {
            __threadfence();
            e = ld_acq(&g_epoch2[0]);
            if (atomicAdd(&g_count2[0], 1) == nctas - 1) {
                g_count2[0] = 0;
                st_rel(&g_epoch2[0], e + 1);
                released = true;
            }
        }

        // ---- tail UNDER the barrier: exp/v/spike + next prefetch ----
        if (tid < 512) {
            float alpha = expf(-1.0f / (tauv + 1e-6f));
            float vn = alpha * vv + (1.0f - alpha) * mv;
            float s = (vn >= th) ? 1.0f : 0.0f;
            vv = vn * (1.0f - s);
            out[((size_t)db * Tq + t) * Dq + n0 + dj] = s;          // spikes
            if (t == Tq - 1)
                out[(size_t)Mq * Dq + (size_t)Bq * Dq + (size_t)db * Dq + n0 + dj] = vv;
            if (t + 1 < Tq) {                                        // prefetch t+1
                xv = __ldcg(&g_xtau[(size_t)((t + 1) * Bq + db) * Dq + n0 + dj]);
                mv = __ldcg(&g_mem [(size_t)((t + 1) * Bq + db) * Dq + n0 + dj]);
            }
        }

        // ---- barrier wait ----
        if (tid == 1023 && !released) {
            unsigned guard = 0;
            while (ld_acq(&g_epoch2[0]) == e) {
                if (++guard > (1u << 20)) break;   // ~130ms escape hatch
                __nanosleep(16);
            }
        }
        __syncthreads();
    }
}

// ============================================================
extern "C" void kernel_launch(void* const* d_in, const int* in_sizes, int n_in,
                              void* d_out, int out_size)
{
    const float* x  = (const float*)d_in[0];
    const float* Wt = (const float*)d_in[1];
    const float* bt = (const float*)d_in[2];
    const float* Wm = (const float*)d_in[3];
    const float* bm = (const float*)d_in[4];
    const float* lt = (const float*)d_in[5];
    float* out = (float*)d_out;

    cudaFuncSetAttribute(scan_kernel,
                         cudaFuncAttributeMaxDynamicSharedMemorySize, SCAN_SMEM);

    dim3 ggrid(Dq / 128, Mq / 128, 2);
    gemm_kernel<<<ggrid, 256>>>(x, Wt, bt, Wm, bm);

    scan_kernel<<<128, 1024, SCAN_SMEM>>>(Wt, lt, out);
}